// round 4
// baseline (speedup 1.0000x reference)
#include <cuda_runtime.h>
#include <math.h>

#define BB   8
#define NN   2048
#define DD   256
#define EE   16
#define HH   8
#define CAPC 256
#define NTOK (BB*NN)
#define EB   (EE*BB)

// ------------------------- device scratch (no allocs) -------------------------
__device__ int   d_idx1[NTOK];
__device__ int   d_idx2[NTOK];
__device__ float d_g1[NTOK];
__device__ float d_g2[NTOK];
__device__ float d_probsum[BB*EE];
__device__ int   d_count1[BB*EE];
__device__ int   d_slot_tok[EB*CAPC];
__device__ float d_U[EB*HH*DD];         // per-(e,b) q projected through Wkv_k
__device__ float d_tlog[NTOK*16];       // token-indexed logits [token][pass][h]
__device__ float d_gates[EB*DD];
__device__ float d_wgT[EE*DD];          // transposed gating weights [e][d]

// ------------------------- init: counters + wg transpose -------------------------
__global__ void k_init(const float* __restrict__ wg) {
    int i = blockIdx.x * blockDim.x + threadIdx.x;
    if (i < BB*EE) { d_probsum[i] = 0.f; d_count1[i] = 0; }
    if (i < EE*DD) {
        int d = i >> 4, e = i & 15;          // i = d*EE + e (coalesced read)
        d_wgT[e*DD + d] = wg[i];
    }
}

// ------------------------- qU: block per (e,b), 1024 threads -------------------------
__global__ void __launch_bounds__(1024, 1) k_qU(
    const float* __restrict__ audio, const float* __restrict__ Wq,
    const float* __restrict__ Wkv)
{
    __shared__ float sa[DD];
    __shared__ float sq[DD];
    __shared__ float sRed[4][DD];

    int e = blockIdx.x >> 3;
    int b = blockIdx.x & 7;
    int tid = threadIdx.x, lane = tid & 31, warp = tid >> 5;
    int g = tid >> 8, wtid = tid & 255;

    if (tid < DD) sa[tid] = audio[b*DD + tid];
    __syncthreads();

    // q[j] = sum_d audio[d]*Wq[e][d][j], 4-way split over d
    const float* Wqe = Wq + (size_t)e*DD*DD;
    {
        float acc = 0.f;
        int d0 = g*64;
#pragma unroll 4
        for (int d = d0; d < d0 + 64; d++) acc += sa[d] * Wqe[d*DD + wtid];
        sRed[g][wtid] = acc;
    }
    __syncthreads();
    if (tid < DD)
        sq[tid] = sRed[0][tid] + sRed[1][tid] + sRed[2][tid] + sRed[3][tid];
    __syncthreads();

    // U[h][d] = sum_t Wkv_k[e][d][h*32+t]*q[h*32+t]; warp = (h, d-quarter)
    const float* Wkve = Wkv + (size_t)e*DD*2*DD;
    {
        int h = warp & 7;
        int dbase = (warp >> 3) * 64;
        float qv = sq[h*32 + lane];
        float* Urow = d_U + ((size_t)blockIdx.x*HH + h)*DD;
#pragma unroll 4
        for (int d = dbase; d < dbase + 64; d++) {
            float v = Wkve[(size_t)d*512 + h*32 + lane] * qv;
#pragma unroll
            for (int off = 16; off > 0; off >>= 1)
                v += __shfl_xor_sync(0xffffffffu, v, off);
            if (lane == 0) Urow[d] = v;
        }
    }
}

// ------------- gating + logits fused: warp per token, one x read -------------
__global__ void k_gatlog(const float* __restrict__ x) {
    __shared__ float sprob[EE];
    __shared__ int   scnt[EE];
    int tid = threadIdx.x;
    if (tid < EE) { sprob[tid] = 0.f; scnt[tid] = 0; }
    __syncthreads();

    int warp = tid >> 5, lane = tid & 31;
    int token = blockIdx.x * 8 + warp;           // 8 tokens per block, same b
    int b = token >> 11;
    const float4* xr4 = (const float4*)(x + (size_t)token * DD);
    float4 xa = xr4[lane], xb = xr4[lane + 32];

    float p[EE];
#pragma unroll
    for (int e = 0; e < EE; e++) {
        const float4* w4 = (const float4*)(d_wgT + e*DD);
        float4 wa = w4[lane], wb = w4[lane + 32];
        p[e] = xa.x*wa.x + xa.y*wa.y + xa.z*wa.z + xa.w*wa.w
             + xb.x*wb.x + xb.y*wb.y + xb.z*wb.z + xb.w*wb.w;
    }
#pragma unroll
    for (int e = 0; e < EE; e++) {
#pragma unroll
        for (int off = 16; off > 0; off >>= 1)
            p[e] += __shfl_xor_sync(0xffffffffu, p[e], off);
    }
    // softmax over 16 (all lanes hold identical p[])
    float mx = p[0];
#pragma unroll
    for (int e = 1; e < EE; e++) mx = fmaxf(mx, p[e]);
    float s = 0.f;
#pragma unroll
    for (int e = 0; e < EE; e++) { p[e] = expf(p[e] - mx); s += p[e]; }
    float inv = 1.f / s;
#pragma unroll
    for (int e = 0; e < EE; e++) p[e] *= inv;
    // top-1 / top-2
    int i1 = 0; float g1v = p[0];
#pragma unroll
    for (int e = 1; e < EE; e++) if (p[e] > g1v) { g1v = p[e]; i1 = e; }
    int i2 = (i1 == 0) ? 1 : 0; float g2v = p[i2];
#pragma unroll
    for (int e = 0; e < EE; e++)
        if (e != i1 && p[e] > g2v) { g2v = p[e]; i2 = e; }
    float denom = g1v + g2v + 1e-9f;

    if (lane == 0) {
        d_idx1[token] = i1; d_idx2[token] = i2;
        d_g1[token] = g1v / denom; d_g2[token] = g2v / denom;
        atomicAdd(&scnt[i1], 1);
    }
    if (lane < EE) atomicAdd(&sprob[lane], p[lane]);

    // ---- logits for both selected experts, token-indexed ----
#pragma unroll
    for (int pass = 0; pass < 2; pass++) {
        int e = (pass == 0) ? i1 : i2;
        const float4* U4 = (const float4*)(d_U + ((size_t)(e*BB + b))*HH*DD);
#pragma unroll
        for (int h = 0; h < HH; h++) {
            float4 ua = U4[h*64 + lane], ub = U4[h*64 + lane + 32];
            float sv = xa.x*ua.x + xa.y*ua.y + xa.z*ua.z + xa.w*ua.w
                     + xb.x*ub.x + xb.y*ub.y + xb.z*ub.z + xb.w*ub.w;
#pragma unroll
            for (int off = 16; off > 0; off >>= 1)
                sv += __shfl_xor_sync(0xffffffffu, sv, off);
            if (lane == 0) d_tlog[(size_t)token*16 + pass*8 + h] = sv;
        }
    }

    __syncthreads();
    if (tid < EE) {
        int bb = (blockIdx.x * 8) >> 11;
        atomicAdd(&d_probsum[bb*EE + tid], sprob[tid]);
        atomicAdd(&d_count1[bb*EE + tid], scnt[tid]);
    }
}

// ------------------------- capacity positions: block per (b,e) -------------------------
__global__ void k_positions() {
    int b = blockIdx.x / EE;
    int e = blockIdx.x % EE;
    int tid = threadIdx.x;                        // 256 threads
    int lane = tid & 31, warp = tid >> 5;
    const int TPT = NN / 256;                     // 8 tokens/thread
    int t0 = tid * TPT;

    __shared__ int wsum[9];
    __shared__ int s_base;
    __shared__ int slots[CAPC];

    slots[tid] = -1;

    // hoist BOTH passes' loads (overlap the L2 round trips)
    int4 a0 = *(const int4*)(d_idx1 + b*NN + t0);
    int4 a1 = *(const int4*)(d_idx1 + b*NN + t0 + 4);
    int4 c0 = *(const int4*)(d_idx2 + b*NN + t0);
    int4 c1 = *(const int4*)(d_idx2 + b*NN + t0 + 4);

    for (int pass = 0; pass < 2; pass++) {
        int mtch[TPT];
        if (pass == 0) {
            mtch[0]=(a0.x==e); mtch[1]=(a0.y==e); mtch[2]=(a0.z==e); mtch[3]=(a0.w==e);
            mtch[4]=(a1.x==e); mtch[5]=(a1.y==e); mtch[6]=(a1.z==e); mtch[7]=(a1.w==e);
        } else {
            mtch[0]=(c0.x==e); mtch[1]=(c0.y==e); mtch[2]=(c0.z==e); mtch[3]=(c0.w==e);
            mtch[4]=(c1.x==e); mtch[5]=(c1.y==e); mtch[6]=(c1.z==e); mtch[7]=(c1.w==e);
        }
        int cnt = 0;
#pragma unroll
        for (int k = 0; k < TPT; k++) cnt += mtch[k];
        int incl = cnt;
#pragma unroll
        for (int off = 1; off < 32; off <<= 1) {
            int v = __shfl_up_sync(0xffffffffu, incl, off);
            if (lane >= off) incl += v;
        }
        int excl = incl - cnt;
        if (lane == 31) wsum[warp] = incl;
        __syncthreads();
        if (tid == 0) {
            int run = 0;
            for (int w = 0; w < 8; w++) { int t = wsum[w]; wsum[w] = run; run += t; }
            wsum[8] = run;
            if (pass == 0) s_base = (run < CAPC) ? run : CAPC;
        }
        __syncthreads();
        int base = excl + wsum[warp] + ((pass == 1) ? s_base : 0);
#pragma unroll
        for (int k = 0; k < TPT; k++) {
            if (mtch[k]) {
                int n = t0 + k;
                if (base < CAPC) {
                    slots[base] = n;
                } else {
                    if (pass == 0) d_g1[b*NN + n] = 0.f;
                    else           d_g2[b*NN + n] = 0.f;
                }
                base++;
            }
        }
        __syncthreads();
    }
    d_slot_tok[(e*BB + b)*CAPC + tid] = slots[tid];
}

// ---------- attn: softmax + y + o + gate fused; block per (e,b), 1024 thr ----------
__global__ void __launch_bounds__(1024, 1) k_attn(
    const float* __restrict__ x, const float* __restrict__ Wkv,
    const float* __restrict__ Wp, const float* __restrict__ bp)
{
    __shared__ int   stok[CAPC];
    __shared__ float satt[HH][CAPC];
    __shared__ float sY[HH][DD];
    __shared__ float sO[DD];
    __shared__ float sRed[4][4][DD];

    int eb = blockIdx.x;
    int e = eb >> 3, b = eb & 7;
    int tid = threadIdx.x, lane = tid & 31, warp = tid >> 5;
    int g = tid >> 8, wtid = tid & 255;

    if (tid < CAPC) stok[tid] = d_slot_tok[eb*CAPC + tid];
    __syncthreads();

    // ---- gather logits slot-wise (thread = slot, 8 heads via 2x float4) ----
    if (tid < CAPC) {
        int tok = stok[tid];
        float4 v0 = make_float4(0.f,0.f,0.f,0.f), v1 = v0;
        if (tok >= 0) {
            int t = b*NN + tok;
            int pass = (d_idx1[t] == e) ? 0 : 1;
            const float4* tl = (const float4*)(d_tlog + (size_t)t*16 + pass*8);
            v0 = tl[0]; v1 = tl[1];
        }
        const float scale = 0.17677669529663687f;   // 32^-0.5
        satt[0][tid] = v0.x*scale; satt[1][tid] = v0.y*scale;
        satt[2][tid] = v0.z*scale; satt[3][tid] = v0.w*scale;
        satt[4][tid] = v1.x*scale; satt[5][tid] = v1.y*scale;
        satt[6][tid] = v1.z*scale; satt[7][tid] = v1.w*scale;
    }
    __syncthreads();

    // ---- softmax per head over 256 slots (warps 0..7) ----
    if (warp < HH) {
        int h = warp;
        float vals[8];
        float mx = -1e30f;
#pragma unroll
        for (int k = 0; k < 8; k++) { vals[k] = satt[h][lane + 32*k]; mx = fmaxf(mx, vals[k]); }
#pragma unroll
        for (int off = 16; off > 0; off >>= 1)
            mx = fmaxf(mx, __shfl_xor_sync(0xffffffffu, mx, off));
        float s = 0.f;
#pragma unroll
        for (int k = 0; k < 8; k++) { vals[k] = expf(vals[k] - mx); s += vals[k]; }
#pragma unroll
        for (int off = 16; off > 0; off >>= 1)
            s += __shfl_xor_sync(0xffffffffu, s, off);
        float inv = 1.f / s;
#pragma unroll
        for (int k = 0; k < 8; k++) satt[h][lane + 32*k] = vals[k] * inv;
    }
    __syncthreads();

    // ---- y[h][d] = sum_c attn[h][c]*Xe[c][d]; group g covers 64 slots ----
    {
        float yv[HH];
#pragma unroll
        for (int h = 0; h < HH; h++) yv[h] = 0.f;
        int c0 = g*64;
        for (int ci = 0; ci < 64; ci++) {
            int c = c0 + ci;
            int tok = stok[c];
            if (tok >= 0) {
                float xv = x[((size_t)b*NN + tok)*DD + wtid];
#pragma unroll
                for (int h = 0; h < HH; h++) yv[h] += satt[h][c] * xv;
            }
        }
#pragma unroll
        for (int r = 0; r < 2; r++) {
            __syncthreads();
#pragma unroll
            for (int hh = 0; hh < 4; hh++) sRed[g][hh][wtid] = yv[r*4 + hh];
            __syncthreads();
            sY[r*4 + g][wtid] = sRed[0][g][wtid] + sRed[1][g][wtid]
                              + sRed[2][g][wtid] + sRed[3][g][wtid];
        }
    }
    __syncthreads();

    // ---- o[j] = sum_d y[h(j)][d]*Wkv_v[e][d][256+j]; 4-way split over d ----
    const float* Wkve = Wkv + (size_t)e*DD*2*DD;
    {
        int h = wtid >> 5;
        float acc = 0.f;
        int d0 = g*64;
#pragma unroll 4
        for (int d = d0; d < d0 + 64; d++)
            acc += sY[h][d] * Wkve[(size_t)d*512 + 256 + wtid];
        sRed[g][0][wtid] = acc;
    }
    __syncthreads();
    if (tid < DD)
        sO[tid] = sRed[0][0][tid] + sRed[1][0][tid] + sRed[2][0][tid] + sRed[3][0][tid];
    __syncthreads();

    // ---- gate[d] = sigmoid(sum_j o[j]*Wp[e][j][d] + bp) ----
    {
        const float* Wpe = Wp + (size_t)e*DD*DD;
        float acc = 0.f;
        int j0 = g*64;
#pragma unroll 4
        for (int j = j0; j < j0 + 64; j++) acc += sO[j] * Wpe[j*DD + wtid];
        sRed[g][1][wtid] = acc;
    }
    __syncthreads();
    if (tid < DD) {
        float gsum = sRed[0][1][tid] + sRed[1][1][tid] + sRed[2][1][tid] + sRed[3][1][tid]
                   + bp[e*DD + tid];
        d_gates[(size_t)eb*DD + tid] = 1.f / (1.f + expf(-gsum));
    }
}

// ------------------------- combine (float4, 4 tokens per block) -------------------------
__global__ void k_combine(const float* __restrict__ x, float* __restrict__ out) {
    int tid = threadIdx.x;
    int token = blockIdx.x*4 + (tid >> 6);
    int q = tid & 63;
    int b = token >> 11;
    int i1 = d_idx1[token], i2 = d_idx2[token];
    float w1 = d_g1[token], w2 = d_g2[token];
    float4 xv = ((const float4*)x)[(size_t)token*64 + q];
    float4 ga = ((const float4*)(d_gates + (i1*BB + b)*DD))[q];
    float4 gb = ((const float4*)(d_gates + (i2*BB + b)*DD))[q];
    float4 o;
    o.x = xv.x * (w1*ga.x + w2*gb.x);
    o.y = xv.y * (w1*ga.y + w2*gb.y);
    o.z = xv.z * (w1*ga.z + w2*gb.z);
    o.w = xv.w * (w1*ga.w + w2*gb.w);
    ((float4*)out)[(size_t)token*64 + q] = o;
}

// ------------------------- loss -------------------------
__global__ void k_loss(float* __restrict__ out, int out_size) {
    __shared__ float red[128];
    int i = threadIdx.x;
    red[i] = d_probsum[i] * (float)d_count1[i];
    __syncthreads();
    for (int s = 64; s > 0; s >>= 1) {
        if (i < s) red[i] += red[i + s];
        __syncthreads();
    }
    if (i == 0 && out_size > BB*NN*DD) {
        float coef = (float)(EE*EE) * 0.01f / ((float)NN * (float)NN * (float)(BB*EE));
        out[BB*NN*DD] = red[0] * coef;
    }
}

// ------------------------- launch -------------------------
extern "C" void kernel_launch(void* const* d_in, const int* in_sizes, int n_in,
                              void* d_out, int out_size) {
    const float* x     = (const float*)d_in[0];
    const float* audio = (const float*)d_in[1];
    const float* wg    = (const float*)d_in[2];
    const float* Wq    = (const float*)d_in[3];
    const float* Wkv   = (const float*)d_in[4];
    const float* Wp    = (const float*)d_in[5];
    const float* bp    = (const float*)d_in[6];
    float* out = (float*)d_out;

    k_init<<<16, 256>>>(wg);
    k_qU<<<EB, 1024>>>(audio, Wq, Wkv);
    k_gatlog<<<NTOK/8, 256>>>(x);
    k_positions<<<BB*EE, 256>>>();
    k_attn<<<EB, 1024>>>(x, Wkv, Wp, bp);
    k_combine<<<NTOK/4, 256>>>(x, out);
    k_loss<<<1, 128>>>(out, out_size);
}